// round 11
// baseline (speedup 1.0000x reference)
#include <cuda_runtime.h>
#include <cuda_bf16.h>
#include <math.h>
#include <stdint.h>

#define SEQ 512
#define BATCH 64
#define NHID 1024
#define G4 4096
#define RBLK 128
#define RTHR 512

__device__ float g_xw[(size_t)SEQ*BATCH*G4];
__device__ float g_c[(size_t)BATCH*NHID];
__device__ unsigned g_cnt[16];                  // per-k64-chunk h readiness
__device__ uint4 g_wt[2][RBLK][16][256];        // recurrence w tiles
__device__ uint4 g_hsplit[2][SEQ+1][16][512];   // h tiles per step [split][t]
__device__ uint4 g_xt[2][512][16][512];         // x tiles (32768 rows)
__device__ uint4 g_wxt[2][64][16][512];         // w_x tiles (4096 rows)
__device__ uint4 g_wot[2][16][16][512];         // w_o tiles (1024 rows)

__device__ __forceinline__ void cp16(uint32_t d,const void*s){
    asm volatile("cp.async.cg.shared.global [%0],[%1],16;"::"r"(d),"l"(s)); }
__device__ __forceinline__ uint32_t s2u(const void*p){
    uint32_t a; asm("{.reg .u64 t; cvta.to.shared.u64 t,%1; cvt.u32.u64 %0,t;}":"=r"(a):"l"(p)); return a; }
__host__ __device__ __forceinline__ uint32_t swz(uint32_t o){ return o^((o>>3)&0x70); }
__device__ __forceinline__ void ldm4(uint32_t*r,uint32_t a){
    asm volatile("ldmatrix.sync.aligned.m8n8.x4.shared.b16 {%0,%1,%2,%3},[%4];"
        :"=r"(r[0]),"=r"(r[1]),"=r"(r[2]),"=r"(r[3]):"r"(a)); }
__device__ __forceinline__ void hmma(float*d,const uint32_t*a,const uint32_t*b){
    asm volatile("mma.sync.aligned.m16n8k16.row.col.f32.bf16.bf16.f32 "
        "{%0,%1,%2,%3},{%4,%5,%6,%7},{%8,%9},{%0,%1,%2,%3};"
        :"+f"(d[0]),"+f"(d[1]),"+f"(d[2]),"+f"(d[3])
        :"r"(a[0]),"r"(a[1]),"r"(a[2]),"r"(a[3]),"r"(b[0]),"r"(b[1])); }
__device__ __forceinline__ void wgrp(int n){
    if(n>=2) asm volatile("cp.async.wait_group 2;"::);
    else if(n==1) asm volatile("cp.async.wait_group 1;"::);
    else asm volatile("cp.async.wait_group 0;"::); }
__device__ __forceinline__ float sigf(float x){
    return __fdividef(1.f, 1.f+__expf(-x)); }
__device__ __forceinline__ float tanhfast(float x){
    return __fdividef(2.f, 1.f+__expf(-2.f*x)) - 1.f; }
__device__ __forceinline__ void waitcnt(int cl, unsigned tgt){
    volatile unsigned* p=&g_cnt[cl];
    while(*p<tgt){}
    __threadfence();
}

// generic fp32 [R][1024] -> pre-swizzled bf16 hi/lo tiles [R/64][16][64][128B]
__global__ void __launch_bounds__(256) prep_tiles(const float* __restrict__ src,
        uint4* __restrict__ th, uint4* __restrict__ tl){
    const int idx=blockIdx.x*256+threadIdx.x;
    const int r=idx>>7, k8=idx&127, ch=k8>>3, kk=k8&7, rb=r>>6, rr=r&63;
    const size_t off=((size_t)(rb*16+ch))*8192 + swz((uint32_t)(rr*128+kk*16));
    const float* s=src+(size_t)r*1024+ch*64+kk*8;
    uint4 uh,ul; __nv_bfloat16*ph=(__nv_bfloat16*)&uh,*pl=(__nv_bfloat16*)&ul;
#pragma unroll
    for(int i=0;i<8;i++){ float v=s[i]; ph[i]=__float2bfloat16(v);
        pl[i]=__float2bfloat16(v-__bfloat162float(ph[i])); }
    *(uint4*)((char*)th+off)=uh;
    *(uint4*)((char*)tl+off)=ul;
}

// recurrence w tiles (block=8 units -> 32 gate rows) + counter reset
__global__ void __launch_bounds__(256) prep_w(const float* __restrict__ w){
    if(blockIdx.x==0&&threadIdx.x<16) g_cnt[threadIdx.x]=0u;
    const int idx=blockIdx.x*256+threadIdx.x;
    const int n=idx>>7, k8=idx&127;
    const int g=n>>10, j=n&1023, bx=j>>3, r=(j&7)*4+g;
    const int ch=k8>>3, kk=k8&7;
    const uint32_t off=swz((uint32_t)(r*128+kk*16));
    const float* s=w+(size_t)n*NHID+ch*64+kk*8;
    uint4 uh,ul; __nv_bfloat16*ph=(__nv_bfloat16*)&uh,*pl=(__nv_bfloat16*)&ul;
#pragma unroll
    for(int i=0;i<8;i++){ float v=s[i]; ph[i]=__float2bfloat16(v);
        pl[i]=__float2bfloat16(v-__bfloat162float(ph[i])); }
    *(uint4*)((char*)&g_wt[0][bx][ch][0]+off)=uh;
    *(uint4*)((char*)&g_wt[1][bx][ch][0]+off)=ul;
}

// HMMA GEMM: C[M,N] = A[M,1024] @ B[N,1024]^T (+bias), bf16-split-3.
#define GBS 65536
__global__ void __launch_bounds__(256,1) hmma_gemm(
    const char* __restrict__ Ah, const char* __restrict__ Al,
    const char* __restrict__ Bh, const char* __restrict__ Bl,
    float* __restrict__ C, const float* __restrict__ bias, int N)
{
    extern __shared__ char sm[];
    const uint32_t S=s2u(sm);
    const int tid=threadIdx.x, lane=tid&31, wid=tid>>5;
    const int rb0=blockIdx.y*2, cb0=blockIdx.x*2;
    const int mi=wid&3, ni=wid>>2;
    const int ar=lane&15;
    const uint32_t axor=(uint32_t)((ar&7)<<4), ahalf=(uint32_t)((lane>>4)*16);
    uint32_t aro[2];
#pragma unroll
    for(int ms=0;ms<2;ms++) aro[ms]=(uint32_t)((mi*32+ms*16+ar)*128);
    const int br=(lane&7)+((lane>>4)&1)*8;
    const uint32_t bxor=(uint32_t)((br&7)<<4), bhalf=(uint32_t)(((lane>>3)&1)*16);

    float d[2][8][4];
#pragma unroll
    for(int a1=0;a1<2;a1++)
#pragma unroll
        for(int a2=0;a2<8;a2++){d[a1][a2][0]=d[a1][a2][1]=d[a1][a2][2]=d[a1][a2][3]=0.f;}

    auto load=[&](int ch){
        const uint32_t bb=S+(uint32_t)(ch%3)*GBS;
#pragma unroll
        for(int q=0;q<8;q++){
            const uint32_t o=(uint32_t)(tid+q*256)*16;
            const int sp=o>>14; const uint32_t rem=o&16383;
            const int rh=rem>>13; const uint32_t win=rem&8191;
            cp16(bb+o, (sp?Al:Ah)+((size_t)((rb0+rh)*16+ch))*8192+win);
        }
#pragma unroll
        for(int q=0;q<8;q++){
            const uint32_t o=(uint32_t)(tid+q*256)*16;
            const int sp=o>>14; const uint32_t rem=o&16383;
            const int rh=rem>>13; const uint32_t win=rem&8191;
            cp16(bb+32768+o, (sp?Bl:Bh)+((size_t)((cb0+rh)*16+ch))*8192+win);
        }
        asm volatile("cp.async.commit_group;"::);
    };

    load(0); load(1);
    for(int c=0;c<16;c++){
        wgrp(c<=14?1:0);
        __syncthreads();
        if(c+2<16) load(c+2);
        const uint32_t AB=S+(uint32_t)(c%3)*GBS;
#pragma unroll
        for(int kq=0;kq<4;kq++){
            const uint32_t ak=((uint32_t)(kq*32)+ahalf)^axor;
            const uint32_t bk=((uint32_t)(kq*32)+bhalf)^bxor;
            uint32_t fA[16];
#pragma unroll
            for(int ms=0;ms<2;ms++)
#pragma unroll
                for(int sp=0;sp<2;sp++)
                    ldm4(fA+ms*8+sp*4, AB+sp*16384+aro[ms]+ak);
#pragma unroll
            for(int n16=0;n16<4;n16++){
                uint32_t fBh[4],fBl[4];
                const uint32_t bro=(uint32_t)((ni*64+n16*16+br)*128);
                ldm4(fBh, AB+32768+bro+bk);
                ldm4(fBl, AB+32768+16384+bro+bk);
#pragma unroll
                for(int ms=0;ms<2;ms++)
#pragma unroll
                    for(int h8=0;h8<2;h8++){
                        float* dd=d[ms][n16*2+h8];
                        hmma(dd, fA+ms*8,   fBh+h8*2);
                        hmma(dd, fA+ms*8,   fBl+h8*2);
                        hmma(dd, fA+ms*8+4, fBh+h8*2);
                    }
            }
        }
    }
    const int row0=blockIdx.y*128, col0=blockIdx.x*128;
#pragma unroll
    for(int ms=0;ms<2;ms++)
#pragma unroll
        for(int n8=0;n8<8;n8++){
            const int r=row0+mi*32+ms*16+(lane>>2);
            const int cc=col0+ni*64+n8*8+(lane&3)*2;
            float b0=0.f,b1=0.f;
            if(bias){ b0=bias[cc]; b1=bias[cc+1]; }
            float2 v0={d[ms][n8][0]+b0, d[ms][n8][1]+b1};
            float2 v1={d[ms][n8][2]+b0, d[ms][n8][3]+b1};
            *(float2*)(C+(size_t)r*N+cc)=v0;
            *(float2*)(C+(size_t)(r+8)*N+cc)=v1;
        }
}

// persistent HMMA recurrence v4: dataflow counters, ping-pong fragments
__global__ void __launch_bounds__(RTHR,1) lstm_mma(const float* __restrict__ c0){
    extern __shared__ char sm[];
    const uint32_t S=s2u(sm), SW=S, SH=S+131072;
    float* Ds=(float*)(sm+131072);
    __nv_bfloat16* hhp=(__nv_bfloat16*)(sm+196608);
    __nv_bfloat16* hlp=(__nv_bfloat16*)(sm+197632);

    const int tid=threadIdx.x, lane=tid&31, wid=tid>>5, bx=blockIdx.x, j0=bx*8;
    const int mi=wid&1, nsub=(wid>>1)&1, kq=wid>>2;
    const int ar=lane&15;
    const uint32_t aklo=(uint32_t)((lane>>4)*16), axor=(uint32_t)((ar&7)<<4);
    uint32_t aoff[2];
#pragma unroll
    for(int ms=0;ms<2;ms++) aoff[ms]=(uint32_t)((mi*32+ms*16+ar)*128);
    const int br=(lane&7)+((lane>>4)&1)*8;
    const uint32_t bklo=(uint32_t)(((lane>>3)&1)*16), bxor=(uint32_t)((br&7)<<4);
    const uint32_t boff=(uint32_t)((nsub*16+br)*128);
    const int eb=tid>>3, eu=tid&7;

#pragma unroll
    for(int sp=0;sp<2;sp++){
        const char* src=(const char*)&g_wt[sp][bx][0][0];
#pragma unroll
        for(int q=0;q<8;q++)
            cp16(SW+sp*65536+(tid+q*512)*16, src+(size_t)(tid+q*512)*16);
    }
    asm volatile("cp.async.commit_group;"::);
    asm volatile("cp.async.wait_group 0;"::);

    float creg=c0[(size_t)eb*NHID+j0+eu];
    __syncthreads();

    for(int t=0;t<SEQ;t++){
        const unsigned tgt=8u*(unsigned)t;
        float xg[4];
        {   const float* xp=g_xw+(size_t)t*BATCH*G4+(size_t)eb*G4+j0+eu;
#pragma unroll
            for(int g=0;g<4;g++) xg[g]=xp[g*1024];
        }
        float d[2][2][4];
#pragma unroll
        for(int a1=0;a1<2;a1++)
#pragma unroll
            for(int a2=0;a2<2;a2++){d[a1][a2][0]=d[a1][a2][1]=d[a1][a2][2]=d[a1][a2][3]=0.f;}

        auto loadh=[&](int cl){
            const uint32_t db=SH+(cl&3)*16384;
            cp16(db+tid*16,      (const char*)&g_hsplit[0][t][cl][0]+(size_t)tid*16);
            cp16(db+8192+tid*16, (const char*)&g_hsplit[1][t][cl][0]+(size_t)tid*16);
            asm volatile("cp.async.commit_group;"::);
        };
        uint32_t fA0[16],fB0[8],fA1[16],fB1[8];
        auto ldfrag2=[&](uint32_t* fA,uint32_t* fB,int c){
            const uint32_t hb=SH+(c&3)*16384;
            const uint32_t wc=SW+c*4096;
            const uint32_t ak=((uint32_t)(kq*32)+aklo)^axor;
            const uint32_t bk=((uint32_t)(kq*32)+bklo)^bxor;
            ldm4(fA+0,  hb+aoff[0]+ak);
            ldm4(fA+4,  hb+aoff[1]+ak);
            ldm4(fA+8,  hb+8192+aoff[0]+ak);
            ldm4(fA+12, hb+8192+aoff[1]+ak);
            ldm4(fB+0,  wc+boff+bk);
            ldm4(fB+4,  wc+65536+boff+bk);
        };
        auto domma=[&](uint32_t* fA,uint32_t* fB){
#pragma unroll
            for(int ms=0;ms<2;ms++)
#pragma unroll
                for(int n8=0;n8<2;n8++){
                    hmma(d[ms][n8], fA+ms*4,   fB+n8*2);
                    hmma(d[ms][n8], fA+ms*4,   fB+4+n8*2);
                    hmma(d[ms][n8], fA+8+ms*4, fB+n8*2);
                }
        };
        // one pipeline slot: wait chunk c's data, refill, prefetch, compute
        auto pipestep=[&](int c,uint32_t* cA,uint32_t* cB,uint32_t* nA,uint32_t* nB){
            if(c+3<16 && tid==0) waitcnt(c+3,tgt);
            wgrp(c<=13?1:0);              // chunk c+1 arrived in smem
            __syncthreads();
            if(c+3<16) loadh(c+3);        // overwrites buf (c-1)&3
            if(c<15) ldfrag2(nA,nB,c+1);
            domma(cA,cB);
        };

        // prologue: wait h[t] chunks 0..2, then stream
        if(tid<3) waitcnt(tid,tgt);
        __syncthreads();
        loadh(0); loadh(1); loadh(2);
        wgrp(2);                          // chunk 0 arrived
        __syncthreads();
        ldfrag2(fA0,fB0,0);

        for(int cc=0;cc<16;cc+=2){
            pipestep(cc,  fA0,fB0, fA1,fB1);
            pipestep(cc+1,fA1,fB1, fA0,fB0);
        }
        __syncthreads();   // all h-buf reads done; Ds may alias now

#pragma unroll
        for(int ms=0;ms<2;ms++)
#pragma unroll
            for(int n8=0;n8<2;n8++){
                const int row=mi*32+ms*16+(lane>>2);
                const int col=nsub*16+n8*8+(lane&3)*2;
                float* p=&Ds[(kq*64+row)*33+col];
                p[0]=d[ms][n8][0]; p[1]=d[ms][n8][1];
                p[33*8]=d[ms][n8][2]; p[33*8+1]=d[ms][n8][3];
            }
        __syncthreads();

        {   float a0=xg[0],a1=xg[1],a2=xg[2],a3=xg[3];
#pragma unroll
            for(int q=0;q<4;q++){
                const float* p=&Ds[(q*64+eb)*33+eu*4];
                a0+=p[0]; a1+=p[1]; a2+=p[2]; a3+=p[3];
            }
            const float iS=sigf(a0), fS=sigf(a1), oS=sigf(a2);
            const float gT=tanhfast(a3);
            const float cn=fS*creg+iS*gT; creg=cn;
            const float hv=oS*tanhfast(cn);
            const __nv_bfloat16 hi=__float2bfloat16(hv);
            hhp[eb*8+eu]=hi;
            hlp[eb*8+eu]=__float2bfloat16(hv-__bfloat162float(hi));
        }
        __syncthreads();
        if(tid<64){
            const uint32_t off=swz((uint32_t)(tid*128+(bx&7)*16));
            *(uint4*)((char*)&g_hsplit[0][t+1][bx>>3][0]+off)=*(uint4*)&hhp[tid*8];
            *(uint4*)((char*)&g_hsplit[1][t+1][bx>>3][0]+off)=*(uint4*)&hlp[tid*8];
        }
        __threadfence();                  // release h[t+1] tile
        __syncthreads();
        if(tid==0) atomicAdd(&g_cnt[bx>>3],1u);
        // no grid barrier: blocks flow ahead, gated only by waitcnt
    }
    g_c[(size_t)eb*NHID+j0+eu]=creg;
}

__global__ void copy_tail(float* __restrict__ oh,float* __restrict__ oc){
    const int i=blockIdx.x*blockDim.x+threadIdx.x;
    if(i<BATCH*NHID){
        const int b=i>>10, k=i&1023, ch=k>>6;
        const uint32_t off=swz((uint32_t)(b*128+(k&63)*2));
        const float hi=__bfloat162float(*(const __nv_bfloat16*)((const char*)&g_hsplit[0][SEQ][ch][0]+off));
        const float lo=__bfloat162float(*(const __nv_bfloat16*)((const char*)&g_hsplit[1][SEQ][ch][0]+off));
        oh[i]=hi+lo;
        oc[i]=g_c[i];
    }
}

extern "C" void kernel_launch(void* const* d_in,const int* in_sizes,int n_in,
                              void* d_out,int out_size){
    const float* x   =(const float*)d_in[0];
    const float* h0  =(const float*)d_in[1];
    const float* c0  =(const float*)d_in[2];
    const float* w_x =(const float*)d_in[3];
    const float* w_h =(const float*)d_in[4];
    const float* bias=(const float*)d_in[5];
    const float* w_o =(const float*)d_in[6];
    float* out=(float*)d_out;
    float *xw;
    cudaGetSymbolAddress((void**)&xw,g_xw);
    uint4 *xt,*wxt,*wot,*hsp;
    cudaGetSymbolAddress((void**)&xt, g_xt);
    cudaGetSymbolAddress((void**)&wxt,g_wxt);
    cudaGetSymbolAddress((void**)&wot,g_wot);
    cudaGetSymbolAddress((void**)&hsp,g_hsplit);
    const size_t XSP=(size_t)512*16*512;
    const size_t WXSP=(size_t)64*16*512;
    const size_t WOSP=(size_t)16*16*512;
    const size_t HSP1=(size_t)16*512;
    const size_t HSPS=(size_t)(SEQ+1)*16*512;

    static int once=0;
    if(!once){
        cudaFuncSetAttribute(lstm_mma, cudaFuncAttributeMaxDynamicSharedMemorySize,198656);
        cudaFuncSetAttribute(hmma_gemm,cudaFuncAttributeMaxDynamicSharedMemorySize,196608);
        once=1;
    }

    prep_tiles<<<16384,256>>>(x,   xt,  xt+XSP);
    prep_tiles<<<2048, 256>>>(w_x, wxt, wxt+WXSP);
    prep_tiles<<<512,  256>>>(w_o, wot, wot+WOSP);
    prep_tiles<<<32,   256>>>(h0,  hsp, hsp+HSPS);
    prep_w    <<<2048, 256>>>(w_h);

    // Phase 1: xw = x@w_x^T + bias
    {   dim3 g(G4/128,(SEQ*BATCH)/128);
        hmma_gemm<<<g,256,196608>>>((char*)xt,(char*)(xt+XSP),
                                    (char*)wxt,(char*)(wxt+WXSP),
                                    xw,bias,G4); }
    // Phase 2: recurrence
    lstm_mma<<<RBLK,RTHR,198656>>>(c0);
    // Phase 3: pred = H@w_o^T
    {   dim3 g(NHID/128,(SEQ*BATCH)/128);
        hmma_gemm<<<g,256,196608>>>((char*)(hsp+HSP1),(char*)(hsp+HSPS+HSP1),
                                    (char*)wot,(char*)(wot+WOSP),
                                    out,nullptr,NHID); }
    copy_tail<<<(BATCH*NHID+255)/256,256>>>(
        out+(size_t)SEQ*BATCH*NHID,
        out+(size_t)SEQ*BATCH*NHID+BATCH*NHID);
}

// round 12
// speedup vs baseline: 1.1217x; 1.1217x over previous
#include <cuda_runtime.h>
#include <cuda_bf16.h>
#include <math.h>
#include <stdint.h>

#define SEQ 512
#define BATCH 64
#define NHID 1024
#define G4 4096
#define RBLK 128
#define RTHR 512

__device__ float g_xw[(size_t)SEQ*BATCH*G4];
__device__ float g_c[(size_t)BATCH*NHID];
__device__ unsigned g_flags[RBLK];
__device__ uint4 g_wt[2][RBLK][16][256];        // recurrence w tiles
__device__ uint4 g_hsplit[2][SEQ+1][16][512];   // h tiles per step [split][t]
__device__ uint4 g_xt[2][512][16][512];         // x tiles (32768 rows)
__device__ uint4 g_wxt[2][64][16][512];         // w_x tiles (4096 rows)
__device__ uint4 g_wot[2][16][16][512];         // w_o tiles (1024 rows)

__device__ __forceinline__ void cp16(uint32_t d,const void*s){
    asm volatile("cp.async.cg.shared.global [%0],[%1],16;"::"r"(d),"l"(s)); }
__device__ __forceinline__ uint32_t s2u(const void*p){
    uint32_t a; asm("{.reg .u64 t; cvta.to.shared.u64 t,%1; cvt.u32.u64 %0,t;}":"=r"(a):"l"(p)); return a; }
__host__ __device__ __forceinline__ uint32_t swz(uint32_t o){ return o^((o>>3)&0x70); }
__device__ __forceinline__ void ldm4(uint32_t*r,uint32_t a){
    asm volatile("ldmatrix.sync.aligned.m8n8.x4.shared.b16 {%0,%1,%2,%3},[%4];"
        :"=r"(r[0]),"=r"(r[1]),"=r"(r[2]),"=r"(r[3]):"r"(a)); }
__device__ __forceinline__ void hmma(float*d,const uint32_t*a,const uint32_t*b){
    asm volatile("mma.sync.aligned.m16n8k16.row.col.f32.bf16.bf16.f32 "
        "{%0,%1,%2,%3},{%4,%5,%6,%7},{%8,%9},{%0,%1,%2,%3};"
        :"+f"(d[0]),"+f"(d[1]),"+f"(d[2]),"+f"(d[3])
        :"r"(a[0]),"r"(a[1]),"r"(a[2]),"r"(a[3]),"r"(b[0]),"r"(b[1])); }
__device__ __forceinline__ void wgrp(int n){
    if(n>=2) asm volatile("cp.async.wait_group 2;"::);
    else if(n==1) asm volatile("cp.async.wait_group 1;"::);
    else asm volatile("cp.async.wait_group 0;"::); }
__device__ __forceinline__ float sigf(float x){
    return __fdividef(1.f, 1.f+__expf(-x)); }
__device__ __forceinline__ float tanhfast(float x){
    return __fdividef(2.f, 1.f+__expf(-2.f*x)) - 1.f; }

// generic fp32 [R][1024] -> pre-swizzled bf16 hi/lo tiles [R/64][16][64][128B]
__global__ void __launch_bounds__(256) prep_tiles(const float* __restrict__ src,
        uint4* __restrict__ th, uint4* __restrict__ tl){
    const int idx=blockIdx.x*256+threadIdx.x;
    const int r=idx>>7, k8=idx&127, ch=k8>>3, kk=k8&7, rb=r>>6, rr=r&63;
    const size_t off=((size_t)(rb*16+ch))*8192 + swz((uint32_t)(rr*128+kk*16));
    const float* s=src+(size_t)r*1024+ch*64+kk*8;
    uint4 uh,ul; __nv_bfloat16*ph=(__nv_bfloat16*)&uh,*pl=(__nv_bfloat16*)&ul;
#pragma unroll
    for(int i=0;i<8;i++){ float v=s[i]; ph[i]=__float2bfloat16(v);
        pl[i]=__float2bfloat16(v-__bfloat162float(ph[i])); }
    *(uint4*)((char*)th+off)=uh;
    *(uint4*)((char*)tl+off)=ul;
}

// recurrence w tiles (block=8 units -> 32 gate rows)
__global__ void __launch_bounds__(256) prep_w(const float* __restrict__ w){
    const int idx=blockIdx.x*256+threadIdx.x;
    const int n=idx>>7, k8=idx&127;
    const int g=n>>10, j=n&1023, bx=j>>3, r=(j&7)*4+g;
    const int ch=k8>>3, kk=k8&7;
    const uint32_t off=swz((uint32_t)(r*128+kk*16));
    const float* s=w+(size_t)n*NHID+ch*64+kk*8;
    uint4 uh,ul; __nv_bfloat16*ph=(__nv_bfloat16*)&uh,*pl=(__nv_bfloat16*)&ul;
#pragma unroll
    for(int i=0;i<8;i++){ float v=s[i]; ph[i]=__float2bfloat16(v);
        pl[i]=__float2bfloat16(v-__bfloat162float(ph[i])); }
    *(uint4*)((char*)&g_wt[0][bx][ch][0]+off)=uh;
    *(uint4*)((char*)&g_wt[1][bx][ch][0]+off)=ul;
}

// HMMA GEMM: C[M,N] = A[M,1024] @ B[N,1024]^T (+bias), bf16-split-3.
#define GBS 65536
__global__ void __launch_bounds__(256,1) hmma_gemm(
    const char* __restrict__ Ah, const char* __restrict__ Al,
    const char* __restrict__ Bh, const char* __restrict__ Bl,
    float* __restrict__ C, const float* __restrict__ bias, int N)
{
    extern __shared__ char sm[];
    const uint32_t S=s2u(sm);
    const int tid=threadIdx.x, lane=tid&31, wid=tid>>5;
    const int rb0=blockIdx.y*2, cb0=blockIdx.x*2;
    const int mi=wid&3, ni=wid>>2;
    const int ar=lane&15;
    const uint32_t axor=(uint32_t)((ar&7)<<4), ahalf=(uint32_t)((lane>>4)*16);
    uint32_t aro[2];
#pragma unroll
    for(int ms=0;ms<2;ms++) aro[ms]=(uint32_t)((mi*32+ms*16+ar)*128);
    const int br=(lane&7)+((lane>>4)&1)*8;
    const uint32_t bxor=(uint32_t)((br&7)<<4), bhalf=(uint32_t)(((lane>>3)&1)*16);

    float d[2][8][4];
#pragma unroll
    for(int a1=0;a1<2;a1++)
#pragma unroll
        for(int a2=0;a2<8;a2++){d[a1][a2][0]=d[a1][a2][1]=d[a1][a2][2]=d[a1][a2][3]=0.f;}

    auto load=[&](int ch){
        const uint32_t bb=S+(uint32_t)(ch%3)*GBS;
#pragma unroll
        for(int q=0;q<8;q++){
            const uint32_t o=(uint32_t)(tid+q*256)*16;
            const int sp=o>>14; const uint32_t rem=o&16383;
            const int rh=rem>>13; const uint32_t win=rem&8191;
            cp16(bb+o, (sp?Al:Ah)+((size_t)((rb0+rh)*16+ch))*8192+win);
        }
#pragma unroll
        for(int q=0;q<8;q++){
            const uint32_t o=(uint32_t)(tid+q*256)*16;
            const int sp=o>>14; const uint32_t rem=o&16383;
            const int rh=rem>>13; const uint32_t win=rem&8191;
            cp16(bb+32768+o, (sp?Bl:Bh)+((size_t)((cb0+rh)*16+ch))*8192+win);
        }
        asm volatile("cp.async.commit_group;"::);
    };

    load(0); load(1);
    for(int c=0;c<16;c++){
        wgrp(c<=14?1:0);
        __syncthreads();
        if(c+2<16) load(c+2);
        const uint32_t AB=S+(uint32_t)(c%3)*GBS;
#pragma unroll
        for(int kq=0;kq<4;kq++){
            const uint32_t ak=((uint32_t)(kq*32)+ahalf)^axor;
            const uint32_t bk=((uint32_t)(kq*32)+bhalf)^bxor;
            uint32_t fA[16];
#pragma unroll
            for(int ms=0;ms<2;ms++)
#pragma unroll
                for(int sp=0;sp<2;sp++)
                    ldm4(fA+ms*8+sp*4, AB+sp*16384+aro[ms]+ak);
#pragma unroll
            for(int n16=0;n16<4;n16++){
                uint32_t fBh[4],fBl[4];
                const uint32_t bro=(uint32_t)((ni*64+n16*16+br)*128);
                ldm4(fBh, AB+32768+bro+bk);
                ldm4(fBl, AB+32768+16384+bro+bk);
#pragma unroll
                for(int ms=0;ms<2;ms++)
#pragma unroll
                    for(int h8=0;h8<2;h8++){
                        float* dd=d[ms][n16*2+h8];
                        hmma(dd, fA+ms*8,   fBh+h8*2);
                        hmma(dd, fA+ms*8,   fBl+h8*2);
                        hmma(dd, fA+ms*8+4, fBh+h8*2);
                    }
            }
        }
    }
    const int row0=blockIdx.y*128, col0=blockIdx.x*128;
#pragma unroll
    for(int ms=0;ms<2;ms++)
#pragma unroll
        for(int n8=0;n8<8;n8++){
            const int r=row0+mi*32+ms*16+(lane>>2);
            const int cc=col0+ni*64+n8*8+(lane&3)*2;
            float b0=0.f,b1=0.f;
            if(bias){ b0=bias[cc]; b1=bias[cc+1]; }
            float2 v0={d[ms][n8][0]+b0, d[ms][n8][1]+b1};
            float2 v1={d[ms][n8][2]+b0, d[ms][n8][3]+b1};
            *(float2*)(C+(size_t)r*N+cc)=v0;
            *(float2*)(C+(size_t)(r+8)*N+cc)=v1;
        }
}

// persistent HMMA recurrence v5: R10 pipeline + one-hop flag barrier + ping-pong
__global__ void __launch_bounds__(RTHR,1) lstm_mma(const float* __restrict__ c0){
    extern __shared__ char sm[];
    const uint32_t S=s2u(sm), SW=S, SH=S+131072;
    float* Ds=(float*)(sm+131072);
    __nv_bfloat16* hhp=(__nv_bfloat16*)(sm+196608);
    __nv_bfloat16* hlp=(__nv_bfloat16*)(sm+197632);

    const int tid=threadIdx.x, lane=tid&31, wid=tid>>5, bx=blockIdx.x, j0=bx*8;
    const int mi=wid&1, nsub=(wid>>1)&1, kq=wid>>2;
    const int ar=lane&15;
    const uint32_t aklo=(uint32_t)((lane>>4)*16), axor=(uint32_t)((ar&7)<<4);
    uint32_t aoff[2];
#pragma unroll
    for(int ms=0;ms<2;ms++) aoff[ms]=(uint32_t)((mi*32+ms*16+ar)*128);
    const int br=(lane&7)+((lane>>4)&1)*8;
    const uint32_t bklo=(uint32_t)(((lane>>3)&1)*16), bxor=(uint32_t)((br&7)<<4);
    const uint32_t boff=(uint32_t)((nsub*16+br)*128);
    const int eb=tid>>3, eu=tid&7;

#pragma unroll
    for(int sp=0;sp<2;sp++){
        const char* src=(const char*)&g_wt[sp][bx][0][0];
#pragma unroll
        for(int q=0;q<8;q++)
            cp16(SW+sp*65536+(tid+q*512)*16, src+(size_t)(tid+q*512)*16);
    }
    asm volatile("cp.async.commit_group;"::);
    asm volatile("cp.async.wait_group 0;"::);

    float creg=c0[(size_t)eb*NHID+j0+eu];
    const unsigned base=((volatile unsigned*)g_flags)[bx];  // uniform across blocks
    __syncthreads();

    for(int t=0;t<SEQ;t++){
        float xg[4];
        {   const float* xp=g_xw+(size_t)t*BATCH*G4+(size_t)eb*G4+j0+eu;
#pragma unroll
            for(int g=0;g<4;g++) xg[g]=xp[g*1024];
        }
        float d[2][2][4];
#pragma unroll
        for(int a1=0;a1<2;a1++)
#pragma unroll
            for(int a2=0;a2<2;a2++){d[a1][a2][0]=d[a1][a2][1]=d[a1][a2][2]=d[a1][a2][3]=0.f;}

        auto loadh=[&](int cl){
            const uint32_t db=SH+(cl&3)*16384;
            cp16(db+tid*16,      (const char*)&g_hsplit[0][t][cl][0]+(size_t)tid*16);
            cp16(db+8192+tid*16, (const char*)&g_hsplit[1][t][cl][0]+(size_t)tid*16);
            asm volatile("cp.async.commit_group;"::);
        };
        uint32_t fA0[16],fB0[8],fA1[16],fB1[8];
        auto ldfrag2=[&](uint32_t* fA,uint32_t* fB,int c){
            const uint32_t hb=SH+(c&3)*16384;
            const uint32_t wc=SW+c*4096;
            const uint32_t ak=((uint32_t)(kq*32)+aklo)^axor;
            const uint32_t bk=((uint32_t)(kq*32)+bklo)^bxor;
            ldm4(fA+0,  hb+aoff[0]+ak);
            ldm4(fA+4,  hb+aoff[1]+ak);
            ldm4(fA+8,  hb+8192+aoff[0]+ak);
            ldm4(fA+12, hb+8192+aoff[1]+ak);
            ldm4(fB+0,  wc+boff+bk);
            ldm4(fB+4,  wc+65536+boff+bk);
        };
        auto domma=[&](uint32_t* fA,uint32_t* fB){
#pragma unroll
            for(int ms=0;ms<2;ms++)
#pragma unroll
                for(int n8=0;n8<2;n8++){
                    hmma(d[ms][n8], fA+ms*4,   fB+n8*2);
                    hmma(d[ms][n8], fA+ms*4,   fB+4+n8*2);
                    hmma(d[ms][n8], fA+8+ms*4, fB+n8*2);
                }
        };

        loadh(0); loadh(1); loadh(2);
        wgrp(2);
        __syncthreads();
        ldfrag2(fA0,fB0,0);

        for(int cc=0;cc<16;cc+=2){
            // slot cc (current frags 0)
            if(cc+3<16) loadh(cc+3);
            wgrp(cc<=12?2:(cc==13?1:0));
            __syncthreads();
            if(cc<15) ldfrag2(fA1,fB1,cc+1);
            domma(fA0,fB0);
            // slot cc+1 (current frags 1)
            if(cc+4<16) loadh(cc+4);
            wgrp(cc+1<=12?2:(cc+1==13?1:0));
            __syncthreads();
            if(cc+1<15) ldfrag2(fA0,fB0,cc+2);
            domma(fA1,fB1);
        }
        __syncthreads();   // all h-buf reads done; Ds may alias now

#pragma unroll
        for(int ms=0;ms<2;ms++)
#pragma unroll
            for(int n8=0;n8<2;n8++){
                const int row=mi*32+ms*16+(lane>>2);
                const int col=nsub*16+n8*8+(lane&3)*2;
                float* p=&Ds[(kq*64+row)*33+col];
                p[0]=d[ms][n8][0]; p[1]=d[ms][n8][1];
                p[33*8]=d[ms][n8][2]; p[33*8+1]=d[ms][n8][3];
            }
        __syncthreads();

        {   float a0=xg[0],a1=xg[1],a2=xg[2],a3=xg[3];
#pragma unroll
            for(int q=0;q<4;q++){
                const float* p=&Ds[(q*64+eb)*33+eu*4];
                a0+=p[0]; a1+=p[1]; a2+=p[2]; a3+=p[3];
            }
            const float iS=sigf(a0), fS=sigf(a1), oS=sigf(a2);
            const float gT=tanhfast(a3);
            const float cn=fS*creg+iS*gT; creg=cn;
            const float hv=oS*tanhfast(cn);
            const __nv_bfloat16 hi=__float2bfloat16(hv);
            hhp[eb*8+eu]=hi;
            hlp[eb*8+eu]=__float2bfloat16(hv-__bfloat162float(hi));
        }
        __syncthreads();
        if(tid<64){
            const uint32_t off=swz((uint32_t)(tid*128+(bx&7)*16));
            *(uint4*)((char*)&g_hsplit[0][t+1][bx>>3][0]+off)=*(uint4*)&hhp[tid*8];
            *(uint4*)((char*)&g_hsplit[1][t+1][bx>>3][0]+off)=*(uint4*)&hlp[tid*8];
        }
        // ---- one-hop flag barrier ----
        __threadfence();                      // release h[t+1] tile
        __syncthreads();
        const unsigned tgt=base+(unsigned)t+1u;
        if(tid==0) ((volatile unsigned*)g_flags)[bx]=tgt;
        if(tid<RBLK){
            volatile unsigned* f=g_flags+tid;
            while(*f<tgt){}
            __threadfence();                  // acquire producers' tiles
        }
        __syncthreads();
    }
    g_c[(size_t)eb*NHID+j0+eu]=creg;
}

__global__ void copy_tail(float* __restrict__ oh,float* __restrict__ oc){
    const int i=blockIdx.x*blockDim.x+threadIdx.x;
    if(i<BATCH*NHID){
        const int b=i>>10, k=i&1023, ch=k>>6;
        const uint32_t off=swz((uint32_t)(b*128+(k&63)*2));
        const float hi=__bfloat162float(*(const __nv_bfloat16*)((const char*)&g_hsplit[0][SEQ][ch][0]+off));
        const float lo=__bfloat162float(*(const __nv_bfloat16*)((const char*)&g_hsplit[1][SEQ][ch][0]+off));
        oh[i]=hi+lo;
        oc[i]=g_c[i];
    }
}

extern "C" void kernel_launch(void* const* d_in,const int* in_sizes,int n_in,
                              void* d_out,int out_size){
    const float* x   =(const float*)d_in[0];
    const float* h0  =(const float*)d_in[1];
    const float* c0  =(const float*)d_in[2];
    const float* w_x =(const float*)d_in[3];
    const float* w_h =(const float*)d_in[4];
    const float* bias=(const float*)d_in[5];
    const float* w_o =(const float*)d_in[6];
    float* out=(float*)d_out;
    float *xw;
    cudaGetSymbolAddress((void**)&xw,g_xw);
    uint4 *xt,*wxt,*wot,*hsp;
    cudaGetSymbolAddress((void**)&xt, g_xt);
    cudaGetSymbolAddress((void**)&wxt,g_wxt);
    cudaGetSymbolAddress((void**)&wot,g_wot);
    cudaGetSymbolAddress((void**)&hsp,g_hsplit);
    const size_t XSP=(size_t)512*16*512;
    const size_t WXSP=(size_t)64*16*512;
    const size_t WOSP=(size_t)16*16*512;
    const size_t HSP1=(size_t)16*512;
    const size_t HSPS=(size_t)(SEQ+1)*16*512;

    static int once=0;
    if(!once){
        cudaFuncSetAttribute(lstm_mma, cudaFuncAttributeMaxDynamicSharedMemorySize,198656);
        cudaFuncSetAttribute(hmma_gemm,cudaFuncAttributeMaxDynamicSharedMemorySize,196608);
        once=1;
    }

    prep_tiles<<<16384,256>>>(x,   xt,  xt+XSP);
    prep_tiles<<<2048, 256>>>(w_x, wxt, wxt+WXSP);
    prep_tiles<<<512,  256>>>(w_o, wot, wot+WOSP);
    prep_tiles<<<32,   256>>>(h0,  hsp, hsp+HSPS);
    prep_w    <<<2048, 256>>>(w_h);

    // Phase 1: xw = x@w_x^T + bias
    {   dim3 g(G4/128,(SEQ*BATCH)/128);
        hmma_gemm<<<g,256,196608>>>((char*)xt,(char*)(xt+XSP),
                                    (char*)wxt,(char*)(wxt+WXSP),
                                    xw,bias,G4); }
    // Phase 2: recurrence
    lstm_mma<<<RBLK,RTHR,198656>>>(c0);
    // Phase 3: pred = H@w_o^T
    {   dim3 g(NHID/128,(SEQ*BATCH)/128);
        hmma_gemm<<<g,256,196608>>>((char*)(hsp+HSP1),(char*)(hsp+HSPS+HSP1),
                                    (char*)wot,(char*)(wot+WOSP),
                                    out,nullptr,NHID); }
    copy_tail<<<(BATCH*NHID+255)/256,256>>>(
        out+(size_t)SEQ*BATCH*NHID,
        out+(size_t)SEQ*BATCH*NHID+BATCH*NHID);
}

// round 13
// speedup vs baseline: 1.5944x; 1.4215x over previous
#include <cuda_runtime.h>
#include <cuda_bf16.h>
#include <math.h>
#include <stdint.h>

#define SEQ 512
#define BATCH 64
#define NHID 1024
#define G4 4096
#define RBLK 128
#define RTHR 512

__device__ float g_xw[(size_t)SEQ*BATCH*G4];
__device__ float g_c[(size_t)BATCH*NHID];
__device__ unsigned g_gen;
__device__ unsigned g_flags[RBLK];
__device__ uint4 g_wt[2][RBLK][16][256];        // recurrence w tiles
__device__ uint4 g_hsplit[2][SEQ+1][16][512];   // h tiles per step [split][t]
__device__ uint4 g_xt[2][512][16][512];         // x tiles (32768 rows)
__device__ uint4 g_wxt[2][64][16][512];         // w_x tiles (4096 rows)
__device__ uint4 g_wot[2][16][16][512];         // w_o tiles (1024 rows)

__device__ __forceinline__ void cp16(uint32_t d,const void*s){
    asm volatile("cp.async.cg.shared.global [%0],[%1],16;"::"r"(d),"l"(s)); }
__device__ __forceinline__ uint32_t s2u(const void*p){
    uint32_t a; asm("{.reg .u64 t; cvta.to.shared.u64 t,%1; cvt.u32.u64 %0,t;}":"=r"(a):"l"(p)); return a; }
__host__ __device__ __forceinline__ uint32_t swz(uint32_t o){ return o^((o>>3)&0x70); }
__device__ __forceinline__ void ldm4(uint32_t*r,uint32_t a){
    asm volatile("ldmatrix.sync.aligned.m8n8.x4.shared.b16 {%0,%1,%2,%3},[%4];"
        :"=r"(r[0]),"=r"(r[1]),"=r"(r[2]),"=r"(r[3]):"r"(a)); }
__device__ __forceinline__ void hmma(float*d,const uint32_t*a,const uint32_t*b){
    asm volatile("mma.sync.aligned.m16n8k16.row.col.f32.bf16.bf16.f32 "
        "{%0,%1,%2,%3},{%4,%5,%6,%7},{%8,%9},{%0,%1,%2,%3};"
        :"+f"(d[0]),"+f"(d[1]),"+f"(d[2]),"+f"(d[3])
        :"r"(a[0]),"r"(a[1]),"r"(a[2]),"r"(a[3]),"r"(b[0]),"r"(b[1])); }
__device__ __forceinline__ void wgrp(int n){
    if(n>=2) asm volatile("cp.async.wait_group 2;"::);
    else if(n==1) asm volatile("cp.async.wait_group 1;"::);
    else asm volatile("cp.async.wait_group 0;"::); }
__device__ __forceinline__ float sigf(float x){
    return __fdividef(1.f, 1.f+__expf(-x)); }
__device__ __forceinline__ float tanhfast(float x){
    return __fdividef(2.f, 1.f+__expf(-2.f*x)) - 1.f; }

// generic fp32 [R][1024] -> pre-swizzled bf16 hi/lo tiles [R/64][16][64][128B]
__global__ void __launch_bounds__(256) prep_tiles(const float* __restrict__ src,
        uint4* __restrict__ th, uint4* __restrict__ tl){
    const int idx=blockIdx.x*256+threadIdx.x;
    const int r=idx>>7, k8=idx&127, ch=k8>>3, kk=k8&7, rb=r>>6, rr=r&63;
    const size_t off=((size_t)(rb*16+ch))*8192 + swz((uint32_t)(rr*128+kk*16));
    const float* s=src+(size_t)r*1024+ch*64+kk*8;
    uint4 uh,ul; __nv_bfloat16*ph=(__nv_bfloat16*)&uh,*pl=(__nv_bfloat16*)&ul;
#pragma unroll
    for(int i=0;i<8;i++){ float v=s[i]; ph[i]=__float2bfloat16(v);
        pl[i]=__float2bfloat16(v-__bfloat162float(ph[i])); }
    *(uint4*)((char*)th+off)=uh;
    *(uint4*)((char*)tl+off)=ul;
}

// recurrence w tiles (block=8 units -> 32 gate rows)
__global__ void __launch_bounds__(256) prep_w(const float* __restrict__ w){
    const int idx=blockIdx.x*256+threadIdx.x;
    const int n=idx>>7, k8=idx&127;
    const int g=n>>10, j=n&1023, bx=j>>3, r=(j&7)*4+g;
    const int ch=k8>>3, kk=k8&7;
    const uint32_t off=swz((uint32_t)(r*128+kk*16));
    const float* s=w+(size_t)n*NHID+ch*64+kk*8;
    uint4 uh,ul; __nv_bfloat16*ph=(__nv_bfloat16*)&uh,*pl=(__nv_bfloat16*)&ul;
#pragma unroll
    for(int i=0;i<8;i++){ float v=s[i]; ph[i]=__float2bfloat16(v);
        pl[i]=__float2bfloat16(v-__bfloat162float(ph[i])); }
    *(uint4*)((char*)&g_wt[0][bx][ch][0]+off)=uh;
    *(uint4*)((char*)&g_wt[1][bx][ch][0]+off)=ul;
}

// HMMA GEMM: C[M,N] = A[M,1024] @ B[N,1024]^T (+bias), bf16-split-3.
#define GBS 65536
__global__ void __launch_bounds__(256,1) hmma_gemm(
    const char* __restrict__ Ah, const char* __restrict__ Al,
    const char* __restrict__ Bh, const char* __restrict__ Bl,
    float* __restrict__ C, const float* __restrict__ bias, int N)
{
    extern __shared__ char sm[];
    const uint32_t S=s2u(sm);
    const int tid=threadIdx.x, lane=tid&31, wid=tid>>5;
    const int rb0=blockIdx.y*2, cb0=blockIdx.x*2;
    const int mi=wid&3, ni=wid>>2;
    const int ar=lane&15;
    const uint32_t axor=(uint32_t)((ar&7)<<4), ahalf=(uint32_t)((lane>>4)*16);
    uint32_t aro[2];
#pragma unroll
    for(int ms=0;ms<2;ms++) aro[ms]=(uint32_t)((mi*32+ms*16+ar)*128);
    const int br=(lane&7)+((lane>>4)&1)*8;
    const uint32_t bxor=(uint32_t)((br&7)<<4), bhalf=(uint32_t)(((lane>>3)&1)*16);

    float d[2][8][4];
#pragma unroll
    for(int a1=0;a1<2;a1++)
#pragma unroll
        for(int a2=0;a2<8;a2++){d[a1][a2][0]=d[a1][a2][1]=d[a1][a2][2]=d[a1][a2][3]=0.f;}

    auto load=[&](int ch){
        const uint32_t bb=S+(uint32_t)(ch%3)*GBS;
#pragma unroll
        for(int q=0;q<8;q++){
            const uint32_t o=(uint32_t)(tid+q*256)*16;
            const int sp=o>>14; const uint32_t rem=o&16383;
            const int rh=rem>>13; const uint32_t win=rem&8191;
            cp16(bb+o, (sp?Al:Ah)+((size_t)((rb0+rh)*16+ch))*8192+win);
        }
#pragma unroll
        for(int q=0;q<8;q++){
            const uint32_t o=(uint32_t)(tid+q*256)*16;
            const int sp=o>>14; const uint32_t rem=o&16383;
            const int rh=rem>>13; const uint32_t win=rem&8191;
            cp16(bb+32768+o, (sp?Bl:Bh)+((size_t)((cb0+rh)*16+ch))*8192+win);
        }
        asm volatile("cp.async.commit_group;"::);
    };

    load(0); load(1);
    for(int c=0;c<16;c++){
        wgrp(c<=14?1:0);
        __syncthreads();
        if(c+2<16) load(c+2);
        const uint32_t AB=S+(uint32_t)(c%3)*GBS;
#pragma unroll
        for(int kq=0;kq<4;kq++){
            const uint32_t ak=((uint32_t)(kq*32)+ahalf)^axor;
            const uint32_t bk=((uint32_t)(kq*32)+bhalf)^bxor;
            uint32_t fA[16];
#pragma unroll
            for(int ms=0;ms<2;ms++)
#pragma unroll
                for(int sp=0;sp<2;sp++)
                    ldm4(fA+ms*8+sp*4, AB+sp*16384+aro[ms]+ak);
#pragma unroll
            for(int n16=0;n16<4;n16++){
                uint32_t fBh[4],fBl[4];
                const uint32_t bro=(uint32_t)((ni*64+n16*16+br)*128);
                ldm4(fBh, AB+32768+bro+bk);
                ldm4(fBl, AB+32768+16384+bro+bk);
#pragma unroll
                for(int ms=0;ms<2;ms++)
#pragma unroll
                    for(int h8=0;h8<2;h8++){
                        float* dd=d[ms][n16*2+h8];
                        hmma(dd, fA+ms*8,   fBh+h8*2);
                        hmma(dd, fA+ms*8,   fBl+h8*2);
                        hmma(dd, fA+ms*8+4, fBh+h8*2);
                    }
            }
        }
    }
    const int row0=blockIdx.y*128, col0=blockIdx.x*128;
#pragma unroll
    for(int ms=0;ms<2;ms++)
#pragma unroll
        for(int n8=0;n8<8;n8++){
            const int r=row0+mi*32+ms*16+(lane>>2);
            const int cc=col0+ni*64+n8*8+(lane&3)*2;
            float b0=0.f,b1=0.f;
            if(bias){ b0=bias[cc]; b1=bias[cc+1]; }
            float2 v0={d[ms][n8][0]+b0, d[ms][n8][1]+b1};
            float2 v1={d[ms][n8][2]+b0, d[ms][n8][3]+b1};
            *(float2*)(C+(size_t)r*N+cc)=v0;
            *(float2*)(C+(size_t)(r+8)*N+cc)=v1;
        }
}

// persistent HMMA recurrence: R10 pipeline + R10 barrier, ping-pong fragments
__global__ void __launch_bounds__(RTHR,1) lstm_mma(const float* __restrict__ c0){
    extern __shared__ char sm[];
    const uint32_t S=s2u(sm), SW=S, SH=S+131072;
    float* Ds=(float*)(sm+131072);
    __nv_bfloat16* hhp=(__nv_bfloat16*)(sm+196608);
    __nv_bfloat16* hlp=(__nv_bfloat16*)(sm+197632);

    const int tid=threadIdx.x, lane=tid&31, wid=tid>>5, bx=blockIdx.x, j0=bx*8;
    const int mi=wid&1, nsub=(wid>>1)&1, kq=wid>>2;
    const int ar=lane&15;
    const uint32_t aklo=(uint32_t)((lane>>4)*16), axor=(uint32_t)((ar&7)<<4);
    uint32_t aoff[2];
#pragma unroll
    for(int ms=0;ms<2;ms++) aoff[ms]=(uint32_t)((mi*32+ms*16+ar)*128);
    const int br=(lane&7)+((lane>>4)&1)*8;
    const uint32_t bklo=(uint32_t)(((lane>>3)&1)*16), bxor=(uint32_t)((br&7)<<4);
    const uint32_t boff=(uint32_t)((nsub*16+br)*128);
    const int eb=tid>>3, eu=tid&7;

#pragma unroll
    for(int sp=0;sp<2;sp++){
        const char* src=(const char*)&g_wt[sp][bx][0][0];
#pragma unroll
        for(int q=0;q<8;q++)
            cp16(SW+sp*65536+(tid+q*512)*16, src+(size_t)(tid+q*512)*16);
    }
    asm volatile("cp.async.commit_group;"::);
    asm volatile("cp.async.wait_group 0;"::);

    float creg=c0[(size_t)eb*NHID+j0+eu];
    const unsigned g0=*(volatile unsigned*)&g_gen;
    __syncthreads();

    for(int t=0;t<SEQ;t++){
        float xg[4];
        {   const float* xp=g_xw+(size_t)t*BATCH*G4+(size_t)eb*G4+j0+eu;
#pragma unroll
            for(int g=0;g<4;g++) xg[g]=xp[g*1024];
        }
        float d[2][2][4];
#pragma unroll
        for(int a1=0;a1<2;a1++)
#pragma unroll
            for(int a2=0;a2<2;a2++){d[a1][a2][0]=d[a1][a2][1]=d[a1][a2][2]=d[a1][a2][3]=0.f;}

        auto loadh=[&](int cl){
            const uint32_t db=SH+(cl&3)*16384;
            cp16(db+tid*16,      (const char*)&g_hsplit[0][t][cl][0]+(size_t)tid*16);
            cp16(db+8192+tid*16, (const char*)&g_hsplit[1][t][cl][0]+(size_t)tid*16);
            asm volatile("cp.async.commit_group;"::);
        };
        uint32_t fA0[16],fB0[8],fA1[16],fB1[8];
        auto ldfrag2=[&](uint32_t* fA,uint32_t* fB,int c){
            const uint32_t hb=SH+(c&3)*16384;
            const uint32_t wc=SW+c*4096;
            const uint32_t ak=((uint32_t)(kq*32)+aklo)^axor;
            const uint32_t bk=((uint32_t)(kq*32)+bklo)^bxor;
            ldm4(fA+0,  hb+aoff[0]+ak);
            ldm4(fA+4,  hb+aoff[1]+ak);
            ldm4(fA+8,  hb+8192+aoff[0]+ak);
            ldm4(fA+12, hb+8192+aoff[1]+ak);
            ldm4(fB+0,  wc+boff+bk);
            ldm4(fB+4,  wc+65536+boff+bk);
        };
        auto domma=[&](uint32_t* fA,uint32_t* fB){
#pragma unroll
            for(int ms=0;ms<2;ms++)
#pragma unroll
                for(int n8=0;n8<2;n8++){
                    hmma(d[ms][n8], fA+ms*4,   fB+n8*2);
                    hmma(d[ms][n8], fA+ms*4,   fB+4+n8*2);
                    hmma(d[ms][n8], fA+8+ms*4, fB+n8*2);
                }
        };

        loadh(0); loadh(1); loadh(2);
        wgrp(2);
        __syncthreads();
        ldfrag2(fA0,fB0,0);

        for(int cc=0;cc<16;cc+=2){
            // slot cc (current frags = 0)
            if(cc+3<16) loadh(cc+3);
            wgrp(cc<=12?2:(cc==13?1:0));
            __syncthreads();
            if(cc<15) ldfrag2(fA1,fB1,cc+1);
            domma(fA0,fB0);
            // slot cc+1 (current frags = 1)
            if(cc+4<16) loadh(cc+4);
            wgrp(cc+1<=12?2:(cc+1==13?1:0));
            __syncthreads();
            if(cc+1<15) ldfrag2(fA0,fB0,cc+2);
            domma(fA1,fB1);
        }
        __syncthreads();   // all h-buf reads done; Ds may alias now

#pragma unroll
        for(int ms=0;ms<2;ms++)
#pragma unroll
            for(int n8=0;n8<2;n8++){
                const int row=mi*32+ms*16+(lane>>2);
                const int col=nsub*16+n8*8+(lane&3)*2;
                float* p=&Ds[(kq*64+row)*33+col];
                p[0]=d[ms][n8][0]; p[1]=d[ms][n8][1];
                p[33*8]=d[ms][n8][2]; p[33*8+1]=d[ms][n8][3];
            }
        __syncthreads();

        {   float a0=xg[0],a1=xg[1],a2=xg[2],a3=xg[3];
#pragma unroll
            for(int q=0;q<4;q++){
                const float* p=&Ds[(q*64+eb)*33+eu*4];
                a0+=p[0]; a1+=p[1]; a2+=p[2]; a3+=p[3];
            }
            const float iS=sigf(a0), fS=sigf(a1), oS=sigf(a2);
            const float gT=tanhfast(a3);
            const float cn=fS*creg+iS*gT; creg=cn;
            const float hv=oS*tanhfast(cn);
            const __nv_bfloat16 hi=__float2bfloat16(hv);
            hhp[eb*8+eu]=hi;
            hlp[eb*8+eu]=__float2bfloat16(hv-__bfloat162float(hi));
        }
        __syncthreads();
        if(tid<64){
            const uint32_t off=swz((uint32_t)(tid*128+(bx&7)*16));
            *(uint4*)((char*)&g_hsplit[0][t+1][bx>>3][0]+off)=*(uint4*)&hhp[tid*8];
            *(uint4*)((char*)&g_hsplit[1][t+1][bx>>3][0]+off)=*(uint4*)&hlp[tid*8];
        }
        // ---- R10 flag barrier: block0 gathers, others poll g_gen ----
        __threadfence();
        __syncthreads();
        if(tid==0) ((volatile unsigned*)g_flags)[bx]=g0+(unsigned)t+1u;
        if(bx==0){
            if(tid<RBLK){ volatile unsigned* f=g_flags+tid;
                while(*f < g0+(unsigned)t+1u){} }
            __syncthreads();
            if(tid==0){ __threadfence(); *(volatile unsigned*)&g_gen=g0+(unsigned)t+1u; }
        }else{
            if(tid==0){ volatile unsigned* gp=&g_gen;
                while(*gp < g0+(unsigned)t+1u){} }
            __syncthreads();
        }
    }
    g_c[(size_t)eb*NHID+j0+eu]=creg;
}

__global__ void copy_tail(float* __restrict__ oh,float* __restrict__ oc){
    const int i=blockIdx.x*blockDim.x+threadIdx.x;
    if(i<BATCH*NHID){
        const int b=i>>10, k=i&1023, ch=k>>6;
        const uint32_t off=swz((uint32_t)(b*128+(k&63)*2));
        const float hi=__bfloat162float(*(const __nv_bfloat16*)((const char*)&g_hsplit[0][SEQ][ch][0]+off));
        const float lo=__bfloat162float(*(const __nv_bfloat16*)((const char*)&g_hsplit[1][SEQ][ch][0]+off));
        oh[i]=hi+lo;
        oc[i]=g_c[i];
    }
}

extern "C" void kernel_launch(void* const* d_in,const int* in_sizes,int n_in,
                              void* d_out,int out_size){
    const float* x   =(const float*)d_in[0];
    const float* h0  =(const float*)d_in[1];
    const float* c0  =(const float*)d_in[2];
    const float* w_x =(const float*)d_in[3];
    const float* w_h =(const float*)d_in[4];
    const float* bias=(const float*)d_in[5];
    const float* w_o =(const float*)d_in[6];
    float* out=(float*)d_out;
    float *xw;
    cudaGetSymbolAddress((void**)&xw,g_xw);
    uint4 *xt,*wxt,*wot,*hsp;
    cudaGetSymbolAddress((void**)&xt, g_xt);
    cudaGetSymbolAddress((void**)&wxt,g_wxt);
    cudaGetSymbolAddress((void**)&wot,g_wot);
    cudaGetSymbolAddress((void**)&hsp,g_hsplit);
    const size_t XSP=(size_t)512*16*512;
    const size_t WXSP=(size_t)64*16*512;
    const size_t WOSP=(size_t)16*16*512;
    const size_t HSP1=(size_t)16*512;
    const size_t HSPS=(size_t)(SEQ+1)*16*512;

    static int once=0;
    if(!once){
        cudaFuncSetAttribute(lstm_mma, cudaFuncAttributeMaxDynamicSharedMemorySize,198656);
        cudaFuncSetAttribute(hmma_gemm,cudaFuncAttributeMaxDynamicSharedMemorySize,196608);
        once=1;
    }

    prep_tiles<<<16384,256>>>(x,   xt,  xt+XSP);
    prep_tiles<<<2048, 256>>>(w_x, wxt, wxt+WXSP);
    prep_tiles<<<512,  256>>>(w_o, wot, wot+WOSP);
    prep_tiles<<<32,   256>>>(h0,  hsp, hsp+HSPS);
    prep_w    <<<2048, 256>>>(w_h);

    // Phase 1: xw = x@w_x^T + bias
    {   dim3 g(G4/128,(SEQ*BATCH)/128);
        hmma_gemm<<<g,256,196608>>>((char*)xt,(char*)(xt+XSP),
                                    (char*)wxt,(char*)(wxt+WXSP),
                                    xw,bias,G4); }
    // Phase 2: recurrence
    lstm_mma<<<RBLK,RTHR,198656>>>(c0);
    // Phase 3: pred = H@w_o^T
    {   dim3 g(NHID/128,(SEQ*BATCH)/128);
        hmma_gemm<<<g,256,196608>>>((char*)(hsp+HSP1),(char*)(hsp+HSPS+HSP1),
                                    (char*)wot,(char*)(wot+WOSP),
                                    out,nullptr,NHID); }
    copy_tail<<<(BATCH*NHID+255)/256,256>>>(
        out+(size_t)SEQ*BATCH*NHID,
        out+(size_t)SEQ*BATCH*NHID+BATCH*NHID);
}